// round 1
// baseline (speedup 1.0000x reference)
#include <cuda_runtime.h>

#define N_IN  1024
#define N_OUT 512
#define BATCH 128
#define M     (N_IN + 1)   // 1025 word lines (weights + bias row)

// ---- device scratch (no allocations allowed) ----
__device__ unsigned g_maxbits;                 // bitwise max of |weights| (all >= 0)
__device__ float4   g_P[M * N_OUT];            // {Cp, Cn, Ep, En} per (i, j)
__device__ float2   g_LS[M * BATCH];           // {lr, sign} transposed [i][b]

__device__ __forceinline__ float ex2f_(float x) {
    float r; asm("ex2.approx.ftz.f32 %0, %1;" : "=f"(r) : "f"(x)); return r;
}
__device__ __forceinline__ float lg2f_(float x) {
    float r; asm("lg2.approx.ftz.f32 %0, %1;" : "=f"(r) : "f"(x)); return r;
}

// K0: zero the output (it is poisoned) and seed the max with the 0.5 bias value.
__global__ void k_init(float* __restrict__ out) {
    int t = blockIdx.x * blockDim.x + threadIdx.x;
    if (t < BATCH * N_OUT) out[t] = 0.0f;
    if (t == 0) g_maxbits = __float_as_uint(0.5f);
}

// K1: max |w| over w_pos and w_neg (bias 0.5 already seeded). Exact bitwise max.
__global__ void k_max(const float* __restrict__ wp, const float* __restrict__ wn) {
    int t = blockIdx.x * blockDim.x + threadIdx.x;
    int stride = gridDim.x * blockDim.x;
    float m = 0.0f;
    for (int i = t; i < N_IN * N_OUT; i += stride)
        m = fmaxf(m, fmaxf(fabsf(wp[i]), fabsf(wn[i])));
    #pragma unroll
    for (int o = 16; o; o >>= 1)
        m = fmaxf(m, __shfl_xor_sync(0xFFFFFFFFu, m, o));
    if ((threadIdx.x & 31) == 0)
        atomicMax(&g_maxbits, __float_as_uint(m));   // valid: non-negative floats
}

// K2: fold constants into per-(i,j) params:
//   C = 0.5*(w + 0.25*maxw)   [= V_REF*G/(k_V*k_G)],  E = log2(2.8 + 0.2*z)
__global__ void k_params(const float* __restrict__ wp, const float* __restrict__ wn,
                         const float* __restrict__ bp, const float* __restrict__ bn,
                         const float* __restrict__ noise) {
    int t = blockIdx.x * blockDim.x + threadIdx.x;   // over M*N_OUT
    if (t >= M * N_OUT) return;
    int i = t / N_OUT;
    int j = t - i * N_OUT;
    float maxw = __uint_as_float(g_maxbits);
    float off  = 0.25f * maxw;                       // G_MIN/k_G = 0.25*maxw
    float wpv = (i < N_IN) ? wp[i * N_OUT + j] : bp[j];
    float wnv = (i < N_IN) ? wn[i * N_OUT + j] : bn[j];
    // noise row i, interleaved columns (2j, 2j+1) -> float2 index i*512+j == t
    float2 z = reinterpret_cast<const float2*>(noise)[t];
    float4 P;
    P.x = 0.5f * (wpv + off);
    P.y = 0.5f * (wnv + off);
    P.z = lg2f_(2.8f + 0.2f * z.x);
    P.w = lg2f_(2.8f + 0.2f * z.y);
    g_P[t] = P;
}

// K3: per-(b,i) voltage terms: ratio = 2|x|, lr = log2(ratio) = 1 + log2|x|, s = sign(x).
// Stored transposed [i][b] for coalesced reads in the main loop. Bias row: x = 1.
__global__ void k_lr(const float* __restrict__ x) {
    int t = blockIdx.x * blockDim.x + threadIdx.x;   // over M*BATCH
    if (t >= M * BATCH) return;
    int i = t / BATCH;
    int b = t - i * BATCH;
    float xv = (i < N_IN) ? x[b * N_IN + i] : 1.0f;
    float a  = fabsf(xv);
    float lr = lg2f_(a) + 1.0f;                      // -inf when x==0 -> exp2 -> 0 (matches ref)
    float s  = (xv > 0.0f) ? 1.0f : ((xv < 0.0f) ? -1.0f : 0.0f);
    g_LS[t] = make_float2(lr, s);
}

// K4: main reduction. Block = 128 threads (all b) for one output column j.
// grid.y = 2 splits the i-range; exactly 2 atomicAdds per output (commutative -> deterministic).
__global__ void __launch_bounds__(128) k_main(float* __restrict__ out) {
    const int j = blockIdx.x;
    const int b = threadIdx.x;
    const int i0 = blockIdx.y ? 513 : 0;
    const int i1 = blockIdx.y ? M   : 513;

    float acc = 0.0f;
    #pragma unroll 4
    for (int i = i0; i < i1; ++i) {
        float4 p  = __ldg(&g_P[i * N_OUT + j]);      // uniform across block (L1 broadcast)
        float2 ls = g_LS[i * BATCH + b];             // coalesced
        float pp = ex2f_(p.z * ls.x);                // ratio^Ep
        float qq = ex2f_(p.w * ls.x);                // ratio^En
        float d  = fmaf(p.x, pp, -(p.y * qq));       // Cp*pp - Cn*qq
        acc = fmaf(ls.y, d, acc);                    // sign(V) * diff
    }
    atomicAdd(&out[b * N_OUT + j], acc);
}

extern "C" void kernel_launch(void* const* d_in, const int* in_sizes, int n_in,
                              void* d_out, int out_size) {
    const float* x     = (const float*)d_in[0];   // (128, 1024)
    const float* w_pos = (const float*)d_in[1];   // (1024, 512)
    const float* w_neg = (const float*)d_in[2];   // (1024, 512)
    const float* b_pos = (const float*)d_in[3];   // (512,)
    const float* b_neg = (const float*)d_in[4];   // (512,)
    const float* noise = (const float*)d_in[5];   // (1025, 1024)
    float* out = (float*)d_out;                   // (128, 512)

    k_init<<<(BATCH * N_OUT + 255) / 256, 256>>>(out);
    k_max<<<512, 256>>>(w_pos, w_neg);
    k_params<<<(M * N_OUT + 255) / 256, 256>>>(w_pos, w_neg, b_pos, b_neg, noise);
    k_lr<<<(M * BATCH + 255) / 256, 256>>>(x);
    dim3 grid(N_OUT, 2);
    k_main<<<grid, 128>>>(out);
}

// round 2
// speedup vs baseline: 1.9618x; 1.9618x over previous
#include <cuda_runtime.h>

#define N_IN  1024
#define N_OUT 512
#define BATCH 128
#define M     (N_IN + 1)   // 1025 word lines (weights + bias row)
#define TJ    8            // j-columns per block
#define NCH   8            // i-chunks
#define NJT   (N_OUT / TJ) // 64 j-tiles

// ---- device scratch (no allocations allowed) ----
__device__ unsigned g_maxbits;                    // bitwise max of |weights| (monotone, never reset)
__device__ float4   g_P[M * N_OUT];               // {Cp, Cn, Ep, En} per (i, j)
__device__ float2   g_LS[M * BATCH];              // {lr, sign} transposed [i][b]
__device__ float    g_part[NCH * BATCH * N_OUT];  // partial sums [ch][b][j]

__device__ __forceinline__ float ex2f_(float x) {
    float r; asm("ex2.approx.ftz.f32 %0, %1;" : "=f"(r) : "f"(x)); return r;
}
__device__ __forceinline__ float lg2f_(float x) {
    float r; asm("lg2.approx.ftz.f32 %0, %1;" : "=f"(r) : "f"(x)); return r;
}

// K0: (a) max|w| over wp, wn, bias 0.5 folded in (atomicMax on non-negative float bits is
// exact & idempotent -> deterministic across replays without a reset kernel);
// (b) per-(b,i) voltage terms lr = 1 + log2|x|, s = sign(x), stored transposed [i][b].
__global__ void k_prep(const float* __restrict__ wp, const float* __restrict__ wn,
                       const float* __restrict__ x) {
    int t = blockIdx.x * blockDim.x + threadIdx.x;
    int stride = gridDim.x * blockDim.x;

    float mx = 0.5f;
    for (int i = t; i < N_IN * N_OUT; i += stride)
        mx = fmaxf(mx, fmaxf(fabsf(wp[i]), fabsf(wn[i])));
    #pragma unroll
    for (int o = 16; o; o >>= 1)
        mx = fmaxf(mx, __shfl_xor_sync(0xFFFFFFFFu, mx, o));
    if ((threadIdx.x & 31) == 0)
        atomicMax(&g_maxbits, __float_as_uint(mx));

    for (int u = t; u < M * BATCH; u += stride) {
        int i = u / BATCH;
        int b = u - i * BATCH;
        float xv = (i < N_IN) ? x[b * N_IN + i] : 1.0f;
        float lr = lg2f_(fabsf(xv)) + 1.0f;          // log2(2|x|); -inf at x==0 -> ex2 -> 0
        float s  = (xv > 0.0f) ? 1.0f : ((xv < 0.0f) ? -1.0f : 0.0f);
        g_LS[u] = make_float2(lr, s);
    }
}

// K1: fold constants into per-(i,j) params:
//   C = 0.5*(w + 0.25*maxw)  [= V_REF*G/(k_V*k_G)],  E = log2(2.8 + 0.2*z)
__global__ void k_params(const float* __restrict__ wp, const float* __restrict__ wn,
                         const float* __restrict__ bp, const float* __restrict__ bn,
                         const float* __restrict__ noise) {
    int t = blockIdx.x * blockDim.x + threadIdx.x;   // over M*N_OUT
    if (t >= M * N_OUT) return;
    int i = t / N_OUT;
    int j = t - i * N_OUT;
    float off = 0.25f * __uint_as_float(g_maxbits);
    float wpv = (i < N_IN) ? wp[i * N_OUT + j] : bp[j];
    float wnv = (i < N_IN) ? wn[i * N_OUT + j] : bn[j];
    float2 z = reinterpret_cast<const float2*>(noise)[t];  // cols (2j, 2j+1) of row i
    float4 P;
    P.x = 0.5f * (wpv + off);
    P.y = 0.5f * (wnv + off);
    P.z = lg2f_(2.8f + 0.2f * z.x);
    P.w = lg2f_(2.8f + 0.2f * z.y);
    g_P[t] = P;
}

// K2: main. Block = 128 threads (all b), TJ=8 columns per block, NCH i-chunks.
// P tile staged in smem (broadcast reads); ls loaded once per (i,b) and reused 8x.
__global__ void __launch_bounds__(128) k_main() {
    __shared__ float4 sP[(M / NCH + 1) * TJ];        // 129*8 float4 = 16.5 KB

    const int jt = blockIdx.x;                       // 0..63
    const int ch = blockIdx.y;                       // 0..7
    const int j0 = jt * TJ;
    const int i0 = (ch * M) / NCH;
    const int i1 = ((ch + 1) * M) / NCH;
    const int ni = i1 - i0;
    const int b  = threadIdx.x;

    for (int t = b; t < ni * TJ; t += 128) {
        int ii = t >> 3, jj = t & (TJ - 1);
        sP[t] = g_P[(i0 + ii) * N_OUT + j0 + jj];
    }
    __syncthreads();

    float acc[TJ];
    #pragma unroll
    for (int jj = 0; jj < TJ; ++jj) acc[jj] = 0.0f;

    const float2* __restrict__ ls = &g_LS[i0 * BATCH + b];
    #pragma unroll 2
    for (int ii = 0; ii < ni; ++ii) {
        float2 l = ls[ii * BATCH];                   // coalesced, reused for TJ columns
        #pragma unroll
        for (int jj = 0; jj < TJ; ++jj) {
            float4 p = sP[ii * TJ + jj];             // smem broadcast
            float pp = ex2f_(p.z * l.x);             // ratio^Ep
            float qq = ex2f_(p.w * l.x);             // ratio^En
            acc[jj] = fmaf(l.y, fmaf(p.x, pp, -(p.y * qq)), acc[jj]);
        }
    }

    // partials: g_part[(ch*BATCH + b)*N_OUT + j0 .. j0+7]
    float4* dst = reinterpret_cast<float4*>(&g_part[(ch * BATCH + b) * N_OUT + j0]);
    dst[0] = make_float4(acc[0], acc[1], acc[2], acc[3]);
    dst[1] = make_float4(acc[4], acc[5], acc[6], acc[7]);
}

// K3: deterministic fixed-order reduction of NCH partials -> out[b][j].
__global__ void k_reduce(float* __restrict__ out) {
    int t = blockIdx.x * blockDim.x + threadIdx.x;   // t = b*N_OUT + j
    if (t >= BATCH * N_OUT) return;
    float s = 0.0f;
    #pragma unroll
    for (int ch = 0; ch < NCH; ++ch)
        s += g_part[ch * (BATCH * N_OUT) + t];       // coalesced
    out[t] = s;
}

extern "C" void kernel_launch(void* const* d_in, const int* in_sizes, int n_in,
                              void* d_out, int out_size) {
    const float* x     = (const float*)d_in[0];   // (128, 1024)
    const float* w_pos = (const float*)d_in[1];   // (1024, 512)
    const float* w_neg = (const float*)d_in[2];   // (1024, 512)
    const float* b_pos = (const float*)d_in[3];   // (512,)
    const float* b_neg = (const float*)d_in[4];   // (512,)
    const float* noise = (const float*)d_in[5];   // (1025, 1024)
    float* out = (float*)d_out;                   // (128, 512)

    k_prep<<<512, 256>>>(w_pos, w_neg, x);
    k_params<<<(M * N_OUT + 255) / 256, 256>>>(w_pos, w_neg, b_pos, b_neg, noise);
    dim3 grid(NJT, NCH);
    k_main<<<grid, 128>>>();
    k_reduce<<<(BATCH * N_OUT + 255) / 256, 256>>>(out);
}

// round 3
// speedup vs baseline: 3.3344x; 1.6997x over previous
#include <cuda_runtime.h>

#define N_IN  1024
#define N_OUT 512
#define BATCH 128
#define M     (N_IN + 1)    // 1025 word lines (weights + bias row)
#define TJ    8             // j-columns per block
#define NCH   16            // i-chunks
#define NJT   (N_OUT / TJ)  // 64 j-tiles
#define NI_MAX ((M + NCH - 1) / NCH + 1)   // 65

// ---- device scratch (no allocations allowed) ----
__device__ unsigned g_maxbits;                    // bitwise max of |weights| (monotone, idempotent)
__device__ float2   g_LS[M * BATCH];              // {lr, sign} transposed [i][b]
__device__ float    g_part[NCH * BATCH * N_OUT];  // partial sums [ch][b][j]

__device__ __forceinline__ float ex2f_(float x) {
    float r; asm("ex2.approx.ftz.f32 %0, %1;" : "=f"(r) : "f"(x)); return r;
}
__device__ __forceinline__ float lg2f_(float x) {
    float r; asm("lg2.approx.ftz.f32 %0, %1;" : "=f"(r) : "f"(x)); return r;
}

// K0: (a) max|w| (bias 0.5 seeded into the running max; atomicMax on non-negative
// float bits is exact, idempotent across graph replays);
// (b) per-(b,i) terms lr = 1 + log2|x| (= log2(2|x|)), s = sign(x), transposed [i][b].
__global__ void k_prep(const float* __restrict__ wp, const float* __restrict__ wn,
                       const float* __restrict__ x) {
    int t = blockIdx.x * blockDim.x + threadIdx.x;
    int stride = gridDim.x * blockDim.x;

    float mx = 0.5f;
    for (int i = t; i < N_IN * N_OUT; i += stride)
        mx = fmaxf(mx, fmaxf(fabsf(wp[i]), fabsf(wn[i])));
    #pragma unroll
    for (int o = 16; o; o >>= 1)
        mx = fmaxf(mx, __shfl_xor_sync(0xFFFFFFFFu, mx, o));
    if ((threadIdx.x & 31) == 0)
        atomicMax(&g_maxbits, __float_as_uint(mx));

    for (int u = t; u < M * BATCH; u += stride) {
        int i = u / BATCH;
        int b = u - i * BATCH;
        float xv = (i < N_IN) ? x[b * N_IN + i] : 1.0f;
        float lr = lg2f_(fabsf(xv)) + 1.0f;      // -inf at x==0 -> ex2 -> 0, and s==0 kills the term
        float s  = (xv > 0.0f) ? 1.0f : ((xv < 0.0f) ? -1.0f : 0.0f);
        g_LS[u] = make_float2(lr, s);
    }
}

// K1: main. Block = 128 threads (all b), TJ=8 columns, NCH=16 i-chunks.
// Params are computed from the raw inputs during the smem fill (each (i,j) belongs
// to exactly one block, so no global param tensor is needed):
//   Cp = 0.5*(wp + 0.25*maxw), Cn = -0.5*(wn + 0.25*maxw), E = log2(2.8 + 0.2*z)
__global__ void __launch_bounds__(128) k_main(const float* __restrict__ wp,
                                              const float* __restrict__ wn,
                                              const float* __restrict__ bp,
                                              const float* __restrict__ bn,
                                              const float* __restrict__ noise) {
    __shared__ float4 sP[NI_MAX * TJ];           // 65*8*16B = 8.3 KB

    const int jt = blockIdx.x;                   // 0..63
    const int ch = blockIdx.y;                   // 0..15
    const int j0 = jt * TJ;
    const int i0 = (ch * M) / NCH;
    const int i1 = ((ch + 1) * M) / NCH;
    const int ni = i1 - i0;
    const int b  = threadIdx.x;

    const float off = 0.25f * __uint_as_float(g_maxbits);

    for (int t = b; t < ni * TJ; t += 128) {
        int ii = t >> 3, jj = t & (TJ - 1);
        int i = i0 + ii, j = j0 + jj;
        float wpv = (i < N_IN) ? wp[i * N_OUT + j] : bp[j];
        float wnv = (i < N_IN) ? wn[i * N_OUT + j] : bn[j];
        float2 z = reinterpret_cast<const float2*>(noise)[i * N_OUT + j]; // cols (2j,2j+1) of row i
        float4 P;
        P.x =  0.5f * (wpv + off);
        P.y = -0.5f * (wnv + off);
        P.z = lg2f_(2.8f + 0.2f * z.x);
        P.w = lg2f_(2.8f + 0.2f * z.y);
        sP[t] = P;
    }
    __syncthreads();

    float acc[TJ];
    #pragma unroll
    for (int jj = 0; jj < TJ; ++jj) acc[jj] = 0.0f;

    const float2* __restrict__ ls = &g_LS[i0 * BATCH + b];
    float2 l = ls[0];
    #pragma unroll 2
    for (int ii = 0; ii < ni; ++ii) {
        float2 lnext = (ii + 1 < ni) ? ls[(ii + 1) * BATCH] : l;  // prefetch next (i,b)
        #pragma unroll
        for (int jj = 0; jj < TJ; ++jj) {
            float4 p = sP[ii * TJ + jj];          // smem broadcast
            float pp = ex2f_(p.z * l.x);          // ratio^Ep
            float qq = ex2f_(p.w * l.x);          // ratio^En
            acc[jj] = fmaf(l.y, fmaf(p.x, pp, p.y * qq), acc[jj]);
        }
        l = lnext;
    }

    float4* dst = reinterpret_cast<float4*>(&g_part[(ch * BATCH + b) * N_OUT + j0]);
    dst[0] = make_float4(acc[0], acc[1], acc[2], acc[3]);
    dst[1] = make_float4(acc[4], acc[5], acc[6], acc[7]);
}

// K2: deterministic fixed-order reduction of NCH partials -> out[b][j].
__global__ void k_reduce(float* __restrict__ out) {
    int t = blockIdx.x * blockDim.x + threadIdx.x;   // t = b*N_OUT + j
    if (t >= BATCH * N_OUT) return;
    float s = 0.0f;
    #pragma unroll
    for (int ch = 0; ch < NCH; ++ch)
        s += g_part[ch * (BATCH * N_OUT) + t];       // coalesced
    out[t] = s;
}

extern "C" void kernel_launch(void* const* d_in, const int* in_sizes, int n_in,
                              void* d_out, int out_size) {
    const float* x     = (const float*)d_in[0];   // (128, 1024)
    const float* w_pos = (const float*)d_in[1];   // (1024, 512)
    const float* w_neg = (const float*)d_in[2];   // (1024, 512)
    const float* b_pos = (const float*)d_in[3];   // (512,)
    const float* b_neg = (const float*)d_in[4];   // (512,)
    const float* noise = (const float*)d_in[5];   // (1025, 1024)
    float* out = (float*)d_out;                   // (128, 512)

    k_prep<<<512, 256>>>(w_pos, w_neg, x);
    dim3 grid(NJT, NCH);
    k_main<<<grid, 128>>>(w_pos, w_neg, b_pos, b_neg, noise);
    k_reduce<<<(BATCH * N_OUT + 255) / 256, 256>>>(out);
}